// round 12
// baseline (speedup 1.0000x reference)
#include <cuda_runtime.h>
#include <cuda_fp16.h>
#include <math.h>

// 3-layer GCN, N=50000, E=800000, dims 128->64->64->32.
// Layer: out[d] = dis[d]*( sum_{s->d} dis[s]*h[s] + dis[d]*h[d] ) + b, h = in@W
// CSR-by-dst gather; CSR build on forked stream concurrent with gemm1.
// hs operands of the two 64-wide gathers stored as fp16 (halves L2 gather
// traffic); all accumulation fp32; layer-3 path fp32.

#define NMAX 50000
#define EMAX 800000

__device__ __half g_hs1h[NMAX * 64];  // gemm1 out (unscaled, fp16)
__device__ __half g_hs2h[NMAX * 64];  // gemm2 out (pre-scaled, fp16)
__device__ float  g_hA [NMAX * 64];   // layer-1 activations (fp32)
__device__ float  g_hB [NMAX * 64];   // layer-2 activations (fp32)
__device__ float  g_hs3[NMAX * 32];   // gemm3 out (pre-scaled, fp32)
__device__ float  g_dis[NMAX];
__device__ int    g_deg[NMAX];
__device__ int    g_scan[NMAX];
__device__ int    g_bsum[64];
__device__ int    g_rowptr[NMAX + 1];
__device__ int    g_cursor[NMAX];
__device__ int    g_col[EMAX];

// ---------------------------------------------------------------------------
// packed f32x2 helpers (sm_103a)
// ---------------------------------------------------------------------------
__device__ __forceinline__ unsigned long long pack2(float a, float b) {
    unsigned long long r;
    asm("mov.b64 %0, {%1, %2};" : "=l"(r) : "f"(a), "f"(b));
    return r;
}
__device__ __forceinline__ unsigned long long ffma2(unsigned long long a,
                                                    unsigned long long b,
                                                    unsigned long long c) {
    unsigned long long d;
    asm("fma.rn.f32x2 %0, %1, %2, %3;" : "=l"(d) : "l"(a), "l"(b), "l"(c));
    return d;
}
__device__ __forceinline__ unsigned long long fmul2(unsigned long long a,
                                                    unsigned long long b) {
    unsigned long long d;
    asm("mul.rn.f32x2 %0, %1, %2;" : "=l"(d) : "l"(a), "l"(b));
    return d;
}
__device__ __forceinline__ void unpack2(unsigned long long v, float& lo, float& hi) {
    asm("mov.b64 {%0, %1}, %2;" : "=f"(lo), "=f"(hi) : "l"(v));
}
__device__ __forceinline__ float4 h4_to_f4(uint2 u) {
    __half2 h0 = *reinterpret_cast<__half2*>(&u.x);
    __half2 h1 = *reinterpret_cast<__half2*>(&u.y);
    float2 f0 = __half22float2(h0);
    float2 f1 = __half22float2(h1);
    return make_float4(f0.x, f0.y, f1.x, f1.y);
}

// ---------------------------------------------------------------------------
// CSR build
// ---------------------------------------------------------------------------
__global__ void deg_count_kernel(const int* __restrict__ dst, int* deg, int e) {
    int q = blockIdx.x * blockDim.x + threadIdx.x;
    int base = q * 4;
    if (base + 4 <= e) {
        int4 d4 = *reinterpret_cast<const int4*>(dst + base);
        atomicAdd(&deg[d4.x], 1);
        atomicAdd(&deg[d4.y], 1);
        atomicAdd(&deg[d4.z], 1);
        atomicAdd(&deg[d4.w], 1);
    } else {
        for (int i = base; i < e; i++) atomicAdd(&deg[dst[i]], 1);
    }
}

__global__ void scan1_kernel(const int* __restrict__ deg, int* scanout,
                             int* bsum, int n) {
    __shared__ int s[1024];
    int i = blockIdx.x * 1024 + threadIdx.x;
    int v = (i < n) ? deg[i] : 0;
    s[threadIdx.x] = v;
    __syncthreads();
#pragma unroll
    for (int off = 1; off < 1024; off <<= 1) {
        int add = (threadIdx.x >= off) ? s[threadIdx.x - off] : 0;
        __syncthreads();
        s[threadIdx.x] += add;
        __syncthreads();
    }
    if (i < n) scanout[i] = s[threadIdx.x];
    if (threadIdx.x == 1023) bsum[blockIdx.x] = s[1023];
}

__global__ void fixup_kernel(const int* __restrict__ scanin,
                             const int* __restrict__ deg,
                             const int* __restrict__ bsum,
                             int* rowptr, int* cursor, float* dis,
                             int n, int e) {
    __shared__ int wsum[8];
    int tile = blockIdx.x >> 2;
    int part = 0;
    for (int j = threadIdx.x; j < tile; j += blockDim.x) part += bsum[j];
#pragma unroll
    for (int off = 16; off > 0; off >>= 1)
        part += __shfl_down_sync(0xFFFFFFFFu, part, off);
    if ((threadIdx.x & 31) == 0) wsum[threadIdx.x >> 5] = part;
    __syncthreads();
    if (threadIdx.x == 0) {
        int b = 0;
#pragma unroll
        for (int w = 0; w < 8; w++) b += wsum[w];
        wsum[0] = b;
    }
    __syncthreads();
    int base = wsum[0];

    int i = blockIdx.x * blockDim.x + threadIdx.x;
    if (i < n) {
        int d = deg[i];
        int rp = scanin[i] - d + base;
        rowptr[i] = rp;
        cursor[i] = rp;
        dis[i] = rsqrtf((float)(d + 1));  // +1 self loop
    }
    if (i == 0) rowptr[n] = e;
}

__global__ void fill_kernel(const int* __restrict__ src,
                            const int* __restrict__ dst,
                            int* cursor, int* col, int e) {
    int q = blockIdx.x * blockDim.x + threadIdx.x;
    int base = q * 4;
    if (base + 4 <= e) {
        int4 s4 = *reinterpret_cast<const int4*>(src + base);
        int4 d4 = *reinterpret_cast<const int4*>(dst + base);
        int p0 = atomicAdd(&cursor[d4.x], 1);
        int p1 = atomicAdd(&cursor[d4.y], 1);
        int p2 = atomicAdd(&cursor[d4.z], 1);
        int p3 = atomicAdd(&cursor[d4.w], 1);
        col[p0] = s4.x;
        col[p1] = s4.y;
        col[p2] = s4.z;
        col[p3] = s4.w;
    } else {
        for (int i = base; i < e; i++) {
            int p = atomicAdd(&cursor[dst[i]], 1);
            col[p] = src[i];
        }
    }
}

// ---------------------------------------------------------------------------
// GEMM: out[row,:] = (in[row,:] @ W) * (PRESCALE ? dis[row] : 1)
// OT = float (fp32 store) or __half (rn-convert store).
// ---------------------------------------------------------------------------
template <int IN, int OUT, bool PRESCALE, typename OT>
__global__ void gemm_kernel(const float* __restrict__ in,
                            const float* __restrict__ W,
                            const float* __restrict__ dis,
                            OT* __restrict__ hs, int n) {
    __shared__ __align__(16) float sW[IN * OUT];
    for (int i = threadIdx.x; i < IN * OUT / 4; i += blockDim.x)
        reinterpret_cast<float4*>(sW)[i] = reinterpret_cast<const float4*>(W)[i];
    __syncthreads();

    int row = blockIdx.x * blockDim.x + threadIdx.x;
    if (row >= n) return;

    unsigned long long acc[OUT / 2];
#pragma unroll
    for (int c = 0; c < OUT / 2; c++) acc[c] = 0ULL;

    const float* xr = in + (size_t)row * IN;
    for (int k0 = 0; k0 < IN; k0 += 4) {
        float4 xv = *reinterpret_cast<const float4*>(xr + k0);
        float xs[4] = {xv.x, xv.y, xv.z, xv.w};
#pragma unroll
        for (int kk = 0; kk < 4; kk++) {
            unsigned long long xx = pack2(xs[kk], xs[kk]);
            const ulonglong2* wr =
                reinterpret_cast<const ulonglong2*>(sW + (k0 + kk) * OUT);
#pragma unroll
            for (int c4 = 0; c4 < OUT / 4; c4++) {
                ulonglong2 w = wr[c4];
                acc[c4 * 2 + 0] = ffma2(xx, w.x, acc[c4 * 2 + 0]);
                acc[c4 * 2 + 1] = ffma2(xx, w.y, acc[c4 * 2 + 1]);
            }
        }
    }

    if (PRESCALE) {
        float d = dis[row];
        unsigned long long dd = pack2(d, d);
#pragma unroll
        for (int c2 = 0; c2 < OUT / 2; c2++) acc[c2] = fmul2(acc[c2], dd);
    }

    if (sizeof(OT) == 2) {  // fp16 store
        __half2* hp = reinterpret_cast<__half2*>((__half*)hs + (size_t)row * OUT);
#pragma unroll
        for (int c2 = 0; c2 < OUT / 2; c2++) {
            float lo, hi;
            unpack2(acc[c2], lo, hi);
            hp[c2] = __floats2half2_rn(lo, hi);
        }
    } else {                // fp32 store
        ulonglong2* hp = reinterpret_cast<ulonglong2*>((float*)hs + (size_t)row * OUT);
#pragma unroll
        for (int c4 = 0; c4 < OUT / 4; c4++) {
            ulonglong2 r;
            r.x = acc[c4 * 2 + 0];
            r.y = acc[c4 * 2 + 1];
            hp[c4] = r;
        }
    }
}

// ---------------------------------------------------------------------------
// fp16-input gather (64-wide): 16 lanes/node, 4 halves (8B) per lane per edge.
// DIS_SRC: hs unscaled -> multiply gathered values by dis[src] (layer 1).
// out fp32: [relu]( dis[d]*acc + b )
// ---------------------------------------------------------------------------
template <bool DIS_SRC>
__global__ void gather_h_kernel(const int* __restrict__ rowptr,
                                const int* __restrict__ col,
                                const __half* __restrict__ hs,
                                const float* __restrict__ dis,
                                const float* __restrict__ bias,
                                float* __restrict__ out, int n) {
    const int G = 16;
    int t = blockIdx.x * blockDim.x + threadIdx.x;
    int gid = t / G;
    int lane = t % G;
    if (gid >= n) return;

    const uint2* hsv = reinterpret_cast<const uint2*>(hs);  // 4 halves per uint2
    int beg = rowptr[gid];
    int end = rowptr[gid + 1];
    float dself = dis[gid];

    float4 a0 = h4_to_f4(hsv[(size_t)gid * G + lane]);  // self term
    if (DIS_SRC) {
        a0.x *= dself; a0.y *= dself; a0.z *= dself; a0.w *= dself;
    }

#pragma unroll 4
    for (int e = beg; e < end; e++) {
        int s = __ldg(&col[e]);
        float4 v = h4_to_f4(__ldg(&hsv[(size_t)s * G + lane]));
        if (DIS_SRC) {
            float ds = __ldg(&dis[s]);
            a0.x += v.x * ds; a0.y += v.y * ds;
            a0.z += v.z * ds; a0.w += v.w * ds;
        } else {
            a0.x += v.x; a0.y += v.y; a0.z += v.z; a0.w += v.w;
        }
    }

    float4 b4 = reinterpret_cast<const float4*>(bias)[lane];
    float4 r;
    r.x = fmaxf(a0.x * dself + b4.x, 0.0f);
    r.y = fmaxf(a0.y * dself + b4.y, 0.0f);
    r.z = fmaxf(a0.z * dself + b4.z, 0.0f);
    r.w = fmaxf(a0.w * dself + b4.w, 0.0f);
    reinterpret_cast<float4*>(out)[(size_t)gid * G + lane] = r;
}

// ---------------------------------------------------------------------------
// fp32 final gather (32-wide): out[d,:] = dis[d]*acc + b, no relu.
// ---------------------------------------------------------------------------
__global__ void gather_f32_kernel(const int* __restrict__ rowptr,
                                  const int* __restrict__ col,
                                  const float* __restrict__ hs,
                                  const float* __restrict__ dis,
                                  const float* __restrict__ bias,
                                  float* __restrict__ out, int n) {
    const int G = 8;  // 32 floats / 4
    int t = blockIdx.x * blockDim.x + threadIdx.x;
    int gid = t / G;
    int lane = t % G;
    if (gid >= n) return;

    const float4* hs4 = reinterpret_cast<const float4*>(hs);
    int beg = rowptr[gid];
    int end = rowptr[gid + 1];

    float dself = dis[gid];
    float4 a0 = hs4[(size_t)gid * G + lane];  // self term

#pragma unroll 4
    for (int e = beg; e < end; e++) {
        int s = __ldg(&col[e]);
        float4 v = hs4[(size_t)s * G + lane];
        a0.x += v.x; a0.y += v.y; a0.z += v.z; a0.w += v.w;
    }

    float4 b4 = reinterpret_cast<const float4*>(bias)[lane];
    float4 r;
    r.x = a0.x * dself + b4.x;
    r.y = a0.y * dself + b4.y;
    r.z = a0.z * dself + b4.z;
    r.w = a0.w * dself + b4.w;
    reinterpret_cast<float4*>(out)[(size_t)gid * G + lane] = r;
}

// ---------------------------------------------------------------------------
// launch
// ---------------------------------------------------------------------------
extern "C" void kernel_launch(void* const* d_in, const int* in_sizes, int n_in,
                              void* d_out, int out_size) {
    const float* x    = (const float*)d_in[0];
    const int*   eidx = (const int*)  d_in[1];
    const float* W1   = (const float*)d_in[2];
    const float* b1   = (const float*)d_in[3];
    const float* W2   = (const float*)d_in[4];
    const float* b2   = (const float*)d_in[5];
    const float* W3   = (const float*)d_in[6];
    const float* b3   = (const float*)d_in[7];

    const int N = in_sizes[0] / 128;
    const int E = in_sizes[1] / 2;
    const int* esrc = eidx;
    const int* edst = eidx + E;

    __half *hs1h, *hs2h;
    float *hA, *hB, *hs3, *dis;
    int *deg, *scn, *bsum, *rowptr, *cursor, *col;
    cudaGetSymbolAddress((void**)&hs1h,   g_hs1h);
    cudaGetSymbolAddress((void**)&hs2h,   g_hs2h);
    cudaGetSymbolAddress((void**)&hA,     g_hA);
    cudaGetSymbolAddress((void**)&hB,     g_hB);
    cudaGetSymbolAddress((void**)&hs3,    g_hs3);
    cudaGetSymbolAddress((void**)&dis,    g_dis);
    cudaGetSymbolAddress((void**)&deg,    g_deg);
    cudaGetSymbolAddress((void**)&scn,    g_scan);
    cudaGetSymbolAddress((void**)&bsum,   g_bsum);
    cudaGetSymbolAddress((void**)&rowptr, g_rowptr);
    cudaGetSymbolAddress((void**)&cursor, g_cursor);
    cudaGetSymbolAddress((void**)&col,    g_col);

    float* out = (float*)d_out;
    const int T = 256;
    const int NB = (N + 1023) / 1024;
    const int EQ = (E + 3) / 4;

    cudaStream_t s2;
    cudaEvent_t evFork, evCSR;
    cudaStreamCreateWithFlags(&s2, cudaStreamNonBlocking);
    cudaEventCreateWithFlags(&evFork, cudaEventDisableTiming);
    cudaEventCreateWithFlags(&evCSR,  cudaEventDisableTiming);

    cudaEventRecord(evFork, 0);
    cudaStreamWaitEvent(s2, evFork, 0);

    // --- CSR build on s2, concurrent with gemm1 on stream 0 ---
    cudaMemsetAsync(deg, 0, (size_t)N * sizeof(int), s2);
    deg_count_kernel<<<(EQ + T - 1) / T, T, 0, s2>>>(edst, deg, E);
    scan1_kernel    <<<NB, 1024, 0, s2>>>(deg, scn, bsum, N);
    fixup_kernel    <<<(N + T - 1) / T, T, 0, s2>>>(scn, deg, bsum,
                                                    rowptr, cursor, dis, N, E);
    fill_kernel     <<<(EQ + T - 1) / T, T, 0, s2>>>(esrc, edst, cursor, col, E);
    cudaEventRecord(evCSR, s2);

    // --- gemm1 (dis-free, fp16 out) on stream 0, concurrent with CSR build ---
    gemm_kernel<128, 64, false, __half><<<(N + 127) / 128, 128>>>(
        x, W1, nullptr, hs1h, N);
    cudaStreamWaitEvent(0, evCSR, 0);

    // --- layer-1 gather (fp16 in, dis on src side), relu -> hA fp32 ---
    gather_h_kernel<true><<<(N * 16 + T - 1) / T, T>>>(
        rowptr, col, hs1h, dis, b1, hA, N);

    // --- gemm2 (pre-scaled, fp16 out) ---
    gemm_kernel<64, 64, true, __half><<<(N + 127) / 128, 128>>>(
        hA, W2, dis, hs2h, N);

    // --- layer-2 gather (fp16 in, pre-scaled), relu -> hB fp32 ---
    gather_h_kernel<false><<<(N * 16 + T - 1) / T, T>>>(
        rowptr, col, hs2h, dis, b2, hB, N);

    // --- gemm3 (pre-scaled, fp32 out) ---
    gemm_kernel<64, 32, true, float><<<(N + 127) / 128, 128>>>(
        hB, W3, dis, hs3, N);

    // --- final gather (fp32) -> out ---
    gather_f32_kernel<<<(N * 8 + T - 1) / T, T>>>(
        rowptr, col, hs3, dis, b3, out, N);

    cudaEventDestroy(evFork);
    cudaEventDestroy(evCSR);
    cudaStreamDestroy(s2);
}